// round 1
// baseline (speedup 1.0000x reference)
#include <cuda_runtime.h>
#include <cuda_bf16.h>

// Problem constants (fixed by the dataset)
#define N_NODES 100000
#define N_EDGES 1600000
#define IN_DIM  64
#define HID_DIM 32

// Scratch (no cudaMalloc allowed): h = (X@W)*norm_src, plus degree counters.
__device__ float g_h[N_NODES * HID_DIM];
__device__ int   g_deg_out[N_NODES];
__device__ int   g_deg_in[N_NODES];

// ---------------------------------------------------------------------------
// Kernel 1: zero d_out (accumulator) and the degree arrays.
// d_out is poisoned to 0xAA by the harness, so this is mandatory.
// ---------------------------------------------------------------------------
__global__ void zero_kernel(float4* __restrict__ out4, int n_out4) {
    int i = blockIdx.x * blockDim.x + threadIdx.x;
    if (i < n_out4) out4[i] = make_float4(0.f, 0.f, 0.f, 0.f);
    if (i < N_NODES) { g_deg_out[i] = 0; g_deg_in[i] = 0; }
}

// ---------------------------------------------------------------------------
// Kernel 2: degree counting. atomicAdd with unused result -> RED in SASS.
// ---------------------------------------------------------------------------
__global__ void degree_kernel(const int* __restrict__ src,
                              const int* __restrict__ dst, int E) {
    int e = blockIdx.x * blockDim.x + threadIdx.x;
    if (e >= E) return;
    atomicAdd(&g_deg_out[src[e]], 1);
    atomicAdd(&g_deg_in[dst[e]], 1);
}

// ---------------------------------------------------------------------------
// Kernel 3: h = (X @ W) * norm_src.   X:[N,64], W:[64,32].
// Block = 256 threads, 32 rows per block (100000 = 3125 * 32 exactly).
// Shared: X tile 8KB + W 8KB. Xs reads broadcast; Ws reads stride-1.
// ---------------------------------------------------------------------------
__global__ __launch_bounds__(256) void gemm_norm_kernel(
    const float* __restrict__ X, const float* __restrict__ W) {
    __shared__ float Xs[32][IN_DIM];
    __shared__ float Ws[IN_DIM][HID_DIM];

    const int tid  = threadIdx.x;
    const int row0 = blockIdx.x * 32;

    // Load W: 64*32 = 2048 floats, 8 per thread.
    #pragma unroll
    for (int i = tid; i < IN_DIM * HID_DIM; i += 256)
        Ws[i / HID_DIM][i % HID_DIM] = W[i];

    // Load X tile: 32*64 = 2048 floats.
    #pragma unroll
    for (int i = tid; i < 32 * IN_DIM; i += 256)
        Xs[i / IN_DIM][i % IN_DIM] = X[(row0 + i / IN_DIM) * IN_DIM + (i % IN_DIM)];

    __syncthreads();

    const int c  = tid & 31;   // output column
    const int r0 = tid >> 5;   // 0..7

    #pragma unroll
    for (int rr = r0; rr < 32; rr += 8) {
        float sum = 0.f;
        #pragma unroll
        for (int k = 0; k < IN_DIM; k++)
            sum = fmaf(Xs[rr][k], Ws[k][c], sum);
        const int row = row0 + rr;
        const int deg = g_deg_out[row];
        const float scale = rsqrtf((float)(deg > 0 ? deg : 1));
        g_h[row * HID_DIM + c] = sum * scale;
    }
}

// ---------------------------------------------------------------------------
// Kernel 4: edge scatter-add.  8 threads per edge, one float4 each.
// out[dst] += h[src] via vectorized red.global.add.v4.f32 (sm_90+).
// h (12.8MB) and out (12.8MB) both fit in L2 -> this is L2-resident traffic.
// ---------------------------------------------------------------------------
__global__ __launch_bounds__(256) void scatter_kernel(
    const int* __restrict__ src, const int* __restrict__ dst,
    float* __restrict__ out, int E) {
    const int t = blockIdx.x * blockDim.x + threadIdx.x;
    const int e = t >> 3;
    const int j = t & 7;
    if (e >= E) return;

    const int s = __ldg(&src[e]);
    const int d = __ldg(&dst[e]);

    const float4 v = __ldg(((const float4*)(g_h + (size_t)s * HID_DIM)) + j);
    float* p = out + (size_t)d * HID_DIM + j * 4;
    asm volatile("red.global.add.v4.f32 [%0], {%1, %2, %3, %4};"
                 :: "l"(p), "f"(v.x), "f"(v.y), "f"(v.z), "f"(v.w)
                 : "memory");
}

// ---------------------------------------------------------------------------
// Kernel 5: out = relu(out * norm_dst + b), in place, float4-vectorized.
// 8 float4 per node row.
// ---------------------------------------------------------------------------
__global__ __launch_bounds__(256) void finalize_kernel(
    float4* __restrict__ out4, const float* __restrict__ b, int n_out4) {
    const int i = blockIdx.x * blockDim.x + threadIdx.x;
    if (i >= n_out4) return;
    const int row = i >> 3;          // 8 float4 per row of 32
    const int j   = i & 7;

    const int deg = g_deg_in[row];
    const float scale = rsqrtf((float)(deg > 0 ? deg : 1));

    const float4 bv = ((const float4*)b)[j];
    float4 v = out4[i];
    v.x = fmaxf(fmaf(v.x, scale, bv.x), 0.f);
    v.y = fmaxf(fmaf(v.y, scale, bv.y), 0.f);
    v.z = fmaxf(fmaf(v.z, scale, bv.z), 0.f);
    v.w = fmaxf(fmaf(v.w, scale, bv.w), 0.f);
    out4[i] = v;
}

// ---------------------------------------------------------------------------
// Launch. Inputs (metadata order): features, src, dst, W, b.
// Output: [N_NODES, HID_DIM] float32.
// ---------------------------------------------------------------------------
extern "C" void kernel_launch(void* const* d_in, const int* in_sizes, int n_in,
                              void* d_out, int out_size) {
    const float* features = (const float*)d_in[0];
    const int*   src      = (const int*)d_in[1];
    const int*   dst      = (const int*)d_in[2];
    const float* W        = (const float*)d_in[3];
    const float* b        = (const float*)d_in[4];
    float*       out      = (float*)d_out;

    const int E = in_sizes[1];
    const int n_out4 = out_size / 4;            // 800000 float4

    // 1. zero accumulator + degrees
    {
        int threads = 256;
        int blocks = (n_out4 + threads - 1) / threads;
        zero_kernel<<<blocks, threads>>>((float4*)out, n_out4);
    }
    // 2. degrees
    {
        int threads = 256;
        int blocks = (E + threads - 1) / threads;
        degree_kernel<<<blocks, threads>>>(src, dst, E);
    }
    // 3. h = (X@W) * norm_src
    {
        gemm_norm_kernel<<<N_NODES / 32, 256>>>(features, W);
    }
    // 4. out[dst] += h[src]
    {
        int threads = 256;
        long long total = (long long)E * 8;
        int blocks = (int)((total + threads - 1) / threads);
        scatter_kernel<<<blocks, threads>>>(src, dst, out, E);
    }
    // 5. out = relu(out * norm_dst + b)
    {
        int threads = 256;
        int blocks = (n_out4 + threads - 1) / threads;
        finalize_kernel<<<blocks, threads>>>((float4*)out, b, n_out4);
    }
}